// round 9
// baseline (speedup 1.0000x reference)
#include <cuda_runtime.h>
#include <cuda_fp16.h>
#include <cuda_bf16.h>
#include <mma.h>

using namespace nvcuda;

// Problem constants.
#define EMB 256
#define MAX_NODES 100000
#define MAX_EDGES 3200000
#define SCAN_BLK 1024
#define MAX_SCAN_BLOCKS 128

// -------- device scratch (no allocations allowed) --------
__device__ __half d_Ph[MAX_NODES * EMB];  // P = emb @ W in fp16 (51.2 MB)
__device__ int   d_rowptr[MAX_NODES + 1];
__device__ int   d_cursor[MAX_NODES + 1];
__device__ int2  d_edge[MAX_EDGES];       // (col, bitcast(val))
__device__ int   d_blocksums[MAX_SCAN_BLOCKS];
__device__ int   d_blockoffs[MAX_SCAN_BLOCKS];

// ---------------- K0a/b/c: zero counts (split in 3 for launch ordering) ----
__global__ void zero_part_kernel(int base, int count) {
    int i = blockIdx.x * blockDim.x + threadIdx.x;
    if (i < count) d_cursor[base + i] = 0;
}

// ---------------- scan helpers ----------------
__device__ __forceinline__ int warp_incl_scan(int v, int lane) {
    #pragma unroll
    for (int off = 1; off < 32; off <<= 1) {
        int x = __shfl_up_sync(0xffffffffu, v, off);
        if (lane >= off) v += x;
    }
    return v;
}

__global__ __launch_bounds__(SCAN_BLK) void scan_block_kernel(int n) {
    __shared__ int wsum[SCAN_BLK / 32];
    const int t = threadIdx.x;
    const int lane = t & 31;
    const int warp = t >> 5;
    const int i = blockIdx.x * SCAN_BLK + t;

    int v = (i < n) ? d_cursor[i] : 0;
    int incl = warp_incl_scan(v, lane);
    if (lane == 31) wsum[warp] = incl;
    __syncthreads();
    if (warp == 0) {
        int s = (lane < SCAN_BLK / 32) ? wsum[lane] : 0;
        s = warp_incl_scan(s, lane);
        if (lane < SCAN_BLK / 32) wsum[lane] = s;
    }
    __syncthreads();
    int base = (warp > 0) ? wsum[warp - 1] : 0;
    if (i < n) d_rowptr[i] = base + incl - v;
    if (t == SCAN_BLK - 1) d_blocksums[blockIdx.x] = base + incl;
}

__global__ __launch_bounds__(128) void scan_sums_kernel(int nblocks, int n) {
    __shared__ int wsum[4];
    const int t = threadIdx.x;
    const int lane = t & 31;
    const int warp = t >> 5;
    int v = (t < nblocks) ? d_blocksums[t] : 0;
    int incl = warp_incl_scan(v, lane);
    if (lane == 31) wsum[warp] = incl;
    __syncthreads();
    if (warp == 0) {
        int s = (lane < 4) ? wsum[lane] : 0;
        s = warp_incl_scan(s, lane);
        if (lane < 4) wsum[lane] = s;
    }
    __syncthreads();
    int base = (warp > 0) ? wsum[warp - 1] : 0;
    if (t < nblocks) d_blockoffs[t] = base + incl - v;
    if (t == 127) d_rowptr[n] = wsum[3];
}

__global__ __launch_bounds__(SCAN_BLK) void scan_add_kernel(int n) {
    const int i = blockIdx.x * SCAN_BLK + threadIdx.x;
    if (i < n) {
        int r = d_rowptr[i] + d_blockoffs[blockIdx.x];
        d_rowptr[i] = r;
        d_cursor[i] = r;
    }
}

// ---------------- K3: scatter edges into CSR order ----------------
__global__ void scatter_kernel(const int* __restrict__ rows,
                               const int* __restrict__ cols,
                               const float* __restrict__ vals, int E) {
    int e = blockIdx.x * blockDim.x + threadIdx.x;
    if (e < E) {
        int r = rows[e];
        int p = atomicAdd(&d_cursor[r], 1);
        d_edge[p] = make_int2(cols[e], __float_as_int(vals[e]));
    }
}

// ---------------- K4: persistent HMMA GEMM + fused edge histogram ---------
// 152 CTAs x 1024 threads. W (256x256 fp16) resident in smem. Each 128-row
// block is processed as two K-chunks of 128 with ping-pong buffers: chunk1
// loads are issued before the chunk0 MMA burst and stored after it, so the
// load latency hides under 32 MMAs/warp. The CTA also histograms its share
// of edges (fire-and-forget L2 atomics, hidden under the GEMM).
#define GBM 128
#define W_LD 264    // W row stride (halfs): 528B, 16B-aligned
#define AC_LD 136   // A chunk row stride (halfs): 272B, 16B-aligned
#define E_LD 20     // epilogue row stride (floats): 80B, 16B-aligned

#define SM_W_BYTES  (256 * W_LD * 2)            // 135168
#define SM_AC_BYTES (GBM * AC_LD * 2)           // 34816 per buffer
#define SM_TOTAL    (SM_W_BYTES + 2 * SM_AC_BYTES)  // 204800 (~200 KB)
// epilogue slab (32*16*E_LD*4 = 40960 B) overlays the two A buffers (69632 B)

extern __shared__ char gemm_smem[];

__global__ __launch_bounds__(1024, 1) void gemm_hist_kernel(
    const float* __restrict__ A, const float* __restrict__ W,
    const int* __restrict__ rows, int E, int M, int nblk) {
    __half (*sWm)[W_LD] = reinterpret_cast<__half(*)[W_LD]>(gemm_smem);
    __half (*sA0)[AC_LD] = reinterpret_cast<__half(*)[AC_LD]>(gemm_smem + SM_W_BYTES);
    __half (*sA1)[AC_LD] = reinterpret_cast<__half(*)[AC_LD]>(gemm_smem + SM_W_BYTES + SM_AC_BYTES);
    float  (*sE)[16][E_LD] = reinterpret_cast<float(*)[16][E_LD]>(gemm_smem + SM_W_BYTES);

    const int tid = threadIdx.x;
    const int warp = tid >> 5;
    const int lane = tid & 31;
    const int warp_m = warp >> 3;   // 0..3 -> m offset 32*warp_m
    const int warp_n = warp & 7;    // 0..7 -> n offset 32*warp_n

    // Convert full W (256x256 fp32) into fp16 smem. 16384 float4, 16/thread.
    #pragma unroll
    for (int i = 0; i < 16; i++) {
        int g = tid + i * 1024;
        int r = g >> 6;            // 64 float4 per row
        int c4 = g & 63;
        float4 b = *reinterpret_cast<const float4*>(&W[r * EMB + c4 * 4]);
        __half2* dst = reinterpret_cast<__half2*>(&sWm[r][c4 * 4]);
        dst[0] = __floats2half2_rn(b.x, b.y);
        dst[1] = __floats2half2_rn(b.z, b.w);
    }

    // Fused histogram: this CTA's contiguous edge chunk. Atomics are
    // fire-and-forget into L2; latency hides under the GEMM below.
    {
        int per = (E + gridDim.x - 1) / gridDim.x;
        int e0 = blockIdx.x * per;
        int e1 = e0 + per; if (e1 > E) e1 = E;
        for (int e = e0 + tid; e < e1; e += 1024)
            atomicAdd(&d_cursor[rows[e]], 1);
    }

    const int a_r = tid >> 5;          // 0..31 base row for staging (32 f4/row)
    const int a_c4 = tid & 31;         // float4 col within 128-wide chunk
    const int er = lane >> 1;          // epilogue row in 16x16 frag
    const int ec0 = (lane & 1) * 8;

    for (int blk = blockIdx.x; blk < nblk; blk += gridDim.x) {
        const int row0 = blk * GBM;

        __syncthreads();   // prev epilogue (overlapping sA) fully read

        // Stage chunk0 (K cols 0..127): 128x32 float4, 4/thread.
        #pragma unroll
        for (int i = 0; i < 4; i++) {
            int r = a_r + i * 32;
            float4 a = {0.f, 0.f, 0.f, 0.f};
            if (row0 + r < M)
                a = *reinterpret_cast<const float4*>(&A[(long)(row0 + r) * EMB + a_c4 * 4]);
            __half2* dst = reinterpret_cast<__half2*>(&sA0[r][a_c4 * 4]);
            dst[0] = __floats2half2_rn(a.x, a.y);
            dst[1] = __floats2half2_rn(a.z, a.w);
        }

        wmma::fragment<wmma::accumulator, 16, 16, 16, float> acc[2][2];
        #pragma unroll
        for (int i = 0; i < 2; i++)
            #pragma unroll
            for (int j = 0; j < 2; j++) wmma::fill_fragment(acc[i][j], 0.f);

        __syncthreads();   // sA0 ready

        // Prefetch chunk1 (K cols 128..255) into registers.
        float4 pf[4];
        #pragma unroll
        for (int i = 0; i < 4; i++) {
            int r = a_r + i * 32;
            pf[i] = make_float4(0.f, 0.f, 0.f, 0.f);
            if (row0 + r < M)
                pf[i] = *reinterpret_cast<const float4*>(&A[(long)(row0 + r) * EMB + 128 + a_c4 * 4]);
        }

        // MMA burst on chunk0: K-steps 0..7, zero barriers.
        #pragma unroll
        for (int ks = 0; ks < 8; ks++) {
            #pragma unroll
            for (int j = 0; j < 2; j++) {
                wmma::fragment<wmma::matrix_b, 16, 16, 16, __half, wmma::row_major> bf;
                wmma::load_matrix_sync(bf, &sWm[ks * 16][warp_n * 32 + j * 16], W_LD);
                #pragma unroll
                for (int i = 0; i < 2; i++) {
                    wmma::fragment<wmma::matrix_a, 16, 16, 16, __half, wmma::row_major> af;
                    wmma::load_matrix_sync(af, &sA0[warp_m * 32 + i * 16][ks * 16], AC_LD);
                    wmma::mma_sync(acc[i][j], af, bf, acc[i][j]);
                }
            }
        }

        // Store prefetched chunk1.
        #pragma unroll
        for (int i = 0; i < 4; i++) {
            int r = a_r + i * 32;
            __half2* dst = reinterpret_cast<__half2*>(&sA1[r][a_c4 * 4]);
            dst[0] = __floats2half2_rn(pf[i].x, pf[i].y);
            dst[1] = __floats2half2_rn(pf[i].z, pf[i].w);
        }
        __syncthreads();   // sA1 ready

        // MMA burst on chunk1: K-steps 8..15.
        #pragma unroll
        for (int ks = 8; ks < 16; ks++) {
            #pragma unroll
            for (int j = 0; j < 2; j++) {
                wmma::fragment<wmma::matrix_b, 16, 16, 16, __half, wmma::row_major> bf;
                wmma::load_matrix_sync(bf, &sWm[ks * 16][warp_n * 32 + j * 16], W_LD);
                #pragma unroll
                for (int i = 0; i < 2; i++) {
                    wmma::fragment<wmma::matrix_a, 16, 16, 16, __half, wmma::row_major> af;
                    wmma::load_matrix_sync(af, &sA1[warp_m * 32 + i * 16][(ks - 8) * 16], AC_LD);
                    wmma::mma_sync(acc[i][j], af, bf, acc[i][j]);
                }
            }
        }

        __syncthreads();   // all MMAs done reading sA; epilogue may overwrite

        // Per-warp epilogue: bounce each 16x16 frag through private slab.
        #pragma unroll
        for (int i = 0; i < 2; i++) {
            #pragma unroll
            for (int j = 0; j < 2; j++) {
                wmma::store_matrix_sync(&sE[warp][0][0], acc[i][j], E_LD, wmma::mem_row_major);
                __syncwarp();
                int g_r = row0 + warp_m * 32 + i * 16 + er;
                if (g_r < M) {
                    float4 v0 = *reinterpret_cast<const float4*>(&sE[warp][er][ec0]);
                    float4 v1 = *reinterpret_cast<const float4*>(&sE[warp][er][ec0 + 4]);
                    __half2 h[4] = {__floats2half2_rn(v0.x, v0.y), __floats2half2_rn(v0.z, v0.w),
                                    __floats2half2_rn(v1.x, v1.y), __floats2half2_rn(v1.z, v1.w)};
                    *reinterpret_cast<uint4*>(&d_Ph[(long)g_r * EMB + warp_n * 32 + j * 16 + ec0]) =
                        *reinterpret_cast<uint4*>(h);
                }
                __syncwarp();
            }
        }
    }
}

// ---------------- K5: SpMM in fp16-P space + ReLU -> fp32 out ----------------
__global__ __launch_bounds__(256) void spmm_relu_kernel(float* __restrict__ out,
                                                        int nrows) {
    const int warp = blockIdx.x * (blockDim.x >> 5) + (threadIdx.x >> 5);
    if (warp >= nrows) return;
    const int lane = threadIdx.x & 31;
    const int s = d_rowptr[warp];
    const int e = d_rowptr[warp + 1];

    float acc[8];
    #pragma unroll
    for (int i = 0; i < 8; i++) acc[i] = 0.f;

    const uint4* __restrict__ Pv = reinterpret_cast<const uint4*>(d_Ph);

    for (int base = s; base < e; base += 32) {
        int idx = base + lane;
        int c = 0;
        float v = 0.f;
        if (idx < e) {
            int2 ev = d_edge[idx];
            c = ev.x;
            v = __int_as_float(ev.y);
        }
        int cnt = e - base; if (cnt > 32) cnt = 32;
        #pragma unroll 2
        for (int j = 0; j < cnt; j++) {
            int   cj = __shfl_sync(0xffffffffu, c, j);
            float vj = __shfl_sync(0xffffffffu, v, j);
            uint4 q = Pv[(long)cj * 32 + lane];
            float2 f0 = __half22float2(*reinterpret_cast<__half2*>(&q.x));
            float2 f1 = __half22float2(*reinterpret_cast<__half2*>(&q.y));
            float2 f2 = __half22float2(*reinterpret_cast<__half2*>(&q.z));
            float2 f3 = __half22float2(*reinterpret_cast<__half2*>(&q.w));
            acc[0] = fmaf(vj, f0.x, acc[0]);
            acc[1] = fmaf(vj, f0.y, acc[1]);
            acc[2] = fmaf(vj, f1.x, acc[2]);
            acc[3] = fmaf(vj, f1.y, acc[3]);
            acc[4] = fmaf(vj, f2.x, acc[4]);
            acc[5] = fmaf(vj, f2.y, acc[5]);
            acc[6] = fmaf(vj, f3.x, acc[6]);
            acc[7] = fmaf(vj, f3.y, acc[7]);
        }
    }
    float4 o0 = {fmaxf(acc[0], 0.f), fmaxf(acc[1], 0.f), fmaxf(acc[2], 0.f), fmaxf(acc[3], 0.f)};
    float4 o1 = {fmaxf(acc[4], 0.f), fmaxf(acc[5], 0.f), fmaxf(acc[6], 0.f), fmaxf(acc[7], 0.f)};
    float4* outv = reinterpret_cast<float4*>(out);
    outv[(long)warp * 64 + lane * 2]     = o0;
    outv[(long)warp * 64 + lane * 2 + 1] = o1;
}

// ---------------- launch ----------------
extern "C" void kernel_launch(void* const* d_in, const int* in_sizes, int n_in,
                              void* d_out, int out_size) {
    const float* emb  = (const float*)d_in[0];
    const int*   rows = (const int*)  d_in[1];
    const int*   cols = (const int*)  d_in[2];
    const float* vals = (const float*)d_in[3];
    const float* W    = (const float*)d_in[4];
    float* out = (float*)d_out;

    const int N = in_sizes[0] / EMB;   // 100000
    const int E = in_sizes[1];         // 3200000

    const int nsb = (N + SCAN_BLK - 1) / SCAN_BLK;
    const int nblk = (N + GBM - 1) / GBM;

    cudaFuncSetAttribute(gemm_hist_kernel, cudaFuncAttributeMaxDynamicSharedMemorySize, SM_TOTAL);

    // zero_counts split in 3 so gemm_hist lands at launch idx 3 (ncu slot).
    const int third = (N + 1 + 2) / 3;
    const int rem = (N + 1) - 2 * third;
    zero_part_kernel<<<(third + 255) / 256, 256>>>(0, third);          // 0
    zero_part_kernel<<<(third + 255) / 256, 256>>>(third, third);      // 1
    zero_part_kernel<<<(rem + 255) / 256, 256>>>(2 * third, rem);      // 2
    gemm_hist_kernel<<<152, 1024, SM_TOTAL>>>(emb, W, rows, E, N, nblk); // 3 <- profiled
    scan_block_kernel<<<nsb, SCAN_BLK>>>(N);                           // 4
    scan_sums_kernel<<<1, 128>>>(nsb, N);                              // 5
    scan_add_kernel<<<nsb, SCAN_BLK>>>(N);                             // 6
    scatter_kernel<<<(E + 511) / 512, 512>>>(rows, cols, vals, E);     // 7
    int warps_per_block = 256 / 32;
    int sgrid = (N + warps_per_block - 1) / warps_per_block;
    spmm_relu_kernel<<<sgrid, 256>>>(out, N);                          // 8
}

// round 10
// speedup vs baseline: 1.0163x; 1.0163x over previous
#include <cuda_runtime.h>
#include <cuda_fp16.h>
#include <cuda_bf16.h>
#include <mma.h>

using namespace nvcuda;

// Problem constants.
#define EMB 256
#define MAX_NODES 100000
#define MAX_EDGES 3200000
#define SCAN_BLK 1024
#define MAX_SCAN_BLOCKS 128

// -------- device scratch (no allocations allowed) --------
__device__ __half d_Ph[MAX_NODES * EMB];  // P = emb @ W in fp16 (51.2 MB)
__device__ int   d_rowptr[MAX_NODES + 1];
__device__ int   d_cursor[MAX_NODES + 1];
__device__ int2  d_edge[MAX_EDGES];       // (col, bitcast(val))
__device__ int   d_blocksums[MAX_SCAN_BLOCKS];
__device__ int   d_blockoffs[MAX_SCAN_BLOCKS];

// ---------------- K0: zero counts ----------------
__global__ void zero_counts_kernel(int n) {
    int i = blockIdx.x * blockDim.x + threadIdx.x;
    if (i <= n) d_cursor[i] = 0;
}

// ---------------- K1: histogram of rows ----------------
__global__ void hist_kernel(const int* __restrict__ rows, int E) {
    int e = blockIdx.x * blockDim.x + threadIdx.x;
    if (e < E) atomicAdd(&d_cursor[rows[e]], 1);
}

// ---------------- scan helpers ----------------
__device__ __forceinline__ int warp_incl_scan(int v, int lane) {
    #pragma unroll
    for (int off = 1; off < 32; off <<= 1) {
        int x = __shfl_up_sync(0xffffffffu, v, off);
        if (lane >= off) v += x;
    }
    return v;
}

__global__ __launch_bounds__(SCAN_BLK) void scan_block_kernel(int n) {
    __shared__ int wsum[SCAN_BLK / 32];
    const int t = threadIdx.x;
    const int lane = t & 31;
    const int warp = t >> 5;
    const int i = blockIdx.x * SCAN_BLK + t;

    int v = (i < n) ? d_cursor[i] : 0;
    int incl = warp_incl_scan(v, lane);
    if (lane == 31) wsum[warp] = incl;
    __syncthreads();
    if (warp == 0) {
        int s = (lane < SCAN_BLK / 32) ? wsum[lane] : 0;
        s = warp_incl_scan(s, lane);
        if (lane < SCAN_BLK / 32) wsum[lane] = s;
    }
    __syncthreads();
    int base = (warp > 0) ? wsum[warp - 1] : 0;
    if (i < n) d_rowptr[i] = base + incl - v;
    if (t == SCAN_BLK - 1) d_blocksums[blockIdx.x] = base + incl;
}

__global__ __launch_bounds__(128) void scan_sums_kernel(int nblocks, int n) {
    __shared__ int wsum[4];
    const int t = threadIdx.x;
    const int lane = t & 31;
    const int warp = t >> 5;
    int v = (t < nblocks) ? d_blocksums[t] : 0;
    int incl = warp_incl_scan(v, lane);
    if (lane == 31) wsum[warp] = incl;
    __syncthreads();
    if (warp == 0) {
        int s = (lane < 4) ? wsum[lane] : 0;
        s = warp_incl_scan(s, lane);
        if (lane < 4) wsum[lane] = s;
    }
    __syncthreads();
    int base = (warp > 0) ? wsum[warp - 1] : 0;
    if (t < nblocks) d_blockoffs[t] = base + incl - v;
    if (t == 127) d_rowptr[n] = wsum[3];
}

__global__ __launch_bounds__(SCAN_BLK) void scan_add_kernel(int n) {
    const int i = blockIdx.x * SCAN_BLK + threadIdx.x;
    if (i < n) {
        int r = d_rowptr[i] + d_blockoffs[blockIdx.x];
        d_rowptr[i] = r;
        d_cursor[i] = r;
    }
}

// ---------------- K3: scatter edges into CSR order ----------------
__global__ void scatter_kernel(const int* __restrict__ rows,
                               const int* __restrict__ cols,
                               const float* __restrict__ vals, int E) {
    int e = blockIdx.x * blockDim.x + threadIdx.x;
    if (e < E) {
        int r = rows[e];
        int p = atomicAdd(&d_cursor[r], 1);
        d_edge[p] = make_int2(cols[e], __float_as_int(vals[e]));
    }
}

// ---------------- K4: persistent HMMA GEMM, W + full A block in smem ------
// 152 CTAs x 1024 threads. W (256x256 fp16) resident; each row-block stages
// the ENTIRE 128x256 A tile, then runs all 16 K-step MMAs with no barriers.
// A-fragments hoisted out of the j-loop (each loaded once per K-step).
// Epilogue slab overlaps the A region (dead after the MMAs).
#define GBM 128
#define AB_LD 264   // 256 + 8 pad (halfs), 528B row stride (16B aligned)
#define E_LD 20     // 16 + 4 pad (floats), 80B row stride (16B aligned)

#define SM_W_BYTES  (256 * AB_LD * 2)           // 135168
#define SM_A_BYTES  (GBM * AB_LD * 2)           // 67584
#define SM_TOTAL    (SM_W_BYTES + SM_A_BYTES)   // 202752 (~198 KB)

extern __shared__ char gemm_smem[];

__global__ __launch_bounds__(1024, 1) void gemm_kernel(const float* __restrict__ A,
                                                       const float* __restrict__ W,
                                                       int M, int nblk) {
    __half (*sWm)[AB_LD] = reinterpret_cast<__half(*)[AB_LD]>(gemm_smem);
    __half (*sA)[AB_LD]  = reinterpret_cast<__half(*)[AB_LD]>(gemm_smem + SM_W_BYTES);
    float  (*sE)[16][E_LD] = reinterpret_cast<float(*)[16][E_LD]>(gemm_smem + SM_W_BYTES);

    const int tid = threadIdx.x;
    const int warp = tid >> 5;
    const int lane = tid & 31;
    const int warp_m = warp >> 3;   // 0..3 -> m offset 32*warp_m
    const int warp_n = warp & 7;    // 0..7 -> n offset 32*warp_n

    // Convert full W (256x256 fp32) into fp16 smem. 16384 float4, 16/thread.
    #pragma unroll
    for (int i = 0; i < 16; i++) {
        int g = tid + i * 1024;
        int r = g >> 6;            // 64 float4 per row
        int c4 = g & 63;
        float4 b = *reinterpret_cast<const float4*>(&W[r * EMB + c4 * 4]);
        __half2* dst = reinterpret_cast<__half2*>(&sWm[r][c4 * 4]);
        dst[0] = __floats2half2_rn(b.x, b.y);
        dst[1] = __floats2half2_rn(b.z, b.w);
    }

    const int er = lane >> 1;      // epilogue row in 16x16 frag
    const int ec0 = (lane & 1) * 8;

    for (int blk = blockIdx.x; blk < nblk; blk += gridDim.x) {
        const int row0 = blk * GBM;

        __syncthreads();   // previous epilogue (overlapping sA) fully read

        // Stage full A block: 128 x 256 fp32 -> fp16. 8192 float4, 8/thread.
        #pragma unroll
        for (int i = 0; i < 8; i++) {
            int g = tid + i * 1024;
            int r = g >> 6;
            int c4 = g & 63;
            float4 a = {0.f, 0.f, 0.f, 0.f};
            if (row0 + r < M)
                a = *reinterpret_cast<const float4*>(&A[(long)(row0 + r) * EMB + c4 * 4]);
            __half2* dst = reinterpret_cast<__half2*>(&sA[r][c4 * 4]);
            dst[0] = __floats2half2_rn(a.x, a.y);
            dst[1] = __floats2half2_rn(a.z, a.w);
        }

        wmma::fragment<wmma::accumulator, 16, 16, 16, float> acc[2][2];
        #pragma unroll
        for (int i = 0; i < 2; i++)
            #pragma unroll
            for (int j = 0; j < 2; j++) wmma::fill_fragment(acc[i][j], 0.f);

        __syncthreads();   // sA ready

        // All 16 K-steps, zero barriers. A-fragments loaded once per K-step.
        #pragma unroll
        for (int ks = 0; ks < 16; ks++) {
            wmma::fragment<wmma::matrix_a, 16, 16, 16, __half, wmma::row_major> af[2];
            #pragma unroll
            for (int i = 0; i < 2; i++)
                wmma::load_matrix_sync(af[i], &sA[warp_m * 32 + i * 16][ks * 16], AB_LD);
            #pragma unroll
            for (int j = 0; j < 2; j++) {
                wmma::fragment<wmma::matrix_b, 16, 16, 16, __half, wmma::row_major> bf;
                wmma::load_matrix_sync(bf, &sWm[ks * 16][warp_n * 32 + j * 16], AB_LD);
                #pragma unroll
                for (int i = 0; i < 2; i++)
                    wmma::mma_sync(acc[i][j], af[i], bf, acc[i][j]);
            }
        }

        __syncthreads();   // all MMAs done reading sA; epilogue may overwrite

        // Per-warp epilogue: bounce each 16x16 frag through private slab.
        #pragma unroll
        for (int i = 0; i < 2; i++) {
            #pragma unroll
            for (int j = 0; j < 2; j++) {
                wmma::store_matrix_sync(&sE[warp][0][0], acc[i][j], E_LD, wmma::mem_row_major);
                __syncwarp();
                int g_r = row0 + warp_m * 32 + i * 16 + er;
                if (g_r < M) {
                    float4 v0 = *reinterpret_cast<const float4*>(&sE[warp][er][ec0]);
                    float4 v1 = *reinterpret_cast<const float4*>(&sE[warp][er][ec0 + 4]);
                    __half2 h[4] = {__floats2half2_rn(v0.x, v0.y), __floats2half2_rn(v0.z, v0.w),
                                    __floats2half2_rn(v1.x, v1.y), __floats2half2_rn(v1.z, v1.w)};
                    *reinterpret_cast<uint4*>(&d_Ph[(long)g_r * EMB + warp_n * 32 + j * 16 + ec0]) =
                        *reinterpret_cast<uint4*>(h);
                }
                __syncwarp();
            }
        }
    }
}

// ---------------- K5: SpMM in fp16-P space + ReLU -> fp32 out ----------------
__global__ __launch_bounds__(256) void spmm_relu_kernel(float* __restrict__ out,
                                                        int nrows) {
    const int warp = blockIdx.x * (blockDim.x >> 5) + (threadIdx.x >> 5);
    if (warp >= nrows) return;
    const int lane = threadIdx.x & 31;
    const int s = d_rowptr[warp];
    const int e = d_rowptr[warp + 1];

    float acc[8];
    #pragma unroll
    for (int i = 0; i < 8; i++) acc[i] = 0.f;

    const uint4* __restrict__ Pv = reinterpret_cast<const uint4*>(d_Ph);

    for (int base = s; base < e; base += 32) {
        int idx = base + lane;
        int c = 0;
        float v = 0.f;
        if (idx < e) {
            int2 ev = d_edge[idx];
            c = ev.x;
            v = __int_as_float(ev.y);
        }
        int cnt = e - base; if (cnt > 32) cnt = 32;
        #pragma unroll 2
        for (int j = 0; j < cnt; j++) {
            int   cj = __shfl_sync(0xffffffffu, c, j);
            float vj = __shfl_sync(0xffffffffu, v, j);
            uint4 q = Pv[(long)cj * 32 + lane];
            float2 f0 = __half22float2(*reinterpret_cast<__half2*>(&q.x));
            float2 f1 = __half22float2(*reinterpret_cast<__half2*>(&q.y));
            float2 f2 = __half22float2(*reinterpret_cast<__half2*>(&q.z));
            float2 f3 = __half22float2(*reinterpret_cast<__half2*>(&q.w));
            acc[0] = fmaf(vj, f0.x, acc[0]);
            acc[1] = fmaf(vj, f0.y, acc[1]);
            acc[2] = fmaf(vj, f1.x, acc[2]);
            acc[3] = fmaf(vj, f1.y, acc[3]);
            acc[4] = fmaf(vj, f2.x, acc[4]);
            acc[5] = fmaf(vj, f2.y, acc[5]);
            acc[6] = fmaf(vj, f3.x, acc[6]);
            acc[7] = fmaf(vj, f3.y, acc[7]);
        }
    }
    float4 o0 = {fmaxf(acc[0], 0.f), fmaxf(acc[1], 0.f), fmaxf(acc[2], 0.f), fmaxf(acc[3], 0.f)};
    float4 o1 = {fmaxf(acc[4], 0.f), fmaxf(acc[5], 0.f), fmaxf(acc[6], 0.f), fmaxf(acc[7], 0.f)};
    float4* outv = reinterpret_cast<float4*>(out);
    outv[(long)warp * 64 + lane * 2]     = o0;
    outv[(long)warp * 64 + lane * 2 + 1] = o1;
}

// ---------------- launch ----------------
extern "C" void kernel_launch(void* const* d_in, const int* in_sizes, int n_in,
                              void* d_out, int out_size) {
    const float* emb  = (const float*)d_in[0];
    const int*   rows = (const int*)  d_in[1];
    const int*   cols = (const int*)  d_in[2];
    const float* vals = (const float*)d_in[3];
    const float* W    = (const float*)d_in[4];
    float* out = (float*)d_out;

    const int N = in_sizes[0] / EMB;   // 100000
    const int E = in_sizes[1];         // 3200000

    const int nsb = (N + SCAN_BLK - 1) / SCAN_BLK;
    const int nblk = (N + GBM - 1) / GBM;

    cudaFuncSetAttribute(gemm_kernel, cudaFuncAttributeMaxDynamicSharedMemorySize, SM_TOTAL);

    // gemm_kernel stays launch idx 3 so ncu profiles it.
    zero_counts_kernel<<<(N + 256) / 256, 256>>>(N);               // 0
    hist_kernel<<<(E + 511) / 512, 512>>>(rows, E);                // 1
    scan_block_kernel<<<nsb, SCAN_BLK>>>(N);                       // 2
    gemm_kernel<<<152, 1024, SM_TOTAL>>>(emb, W, N, nblk);         // 3  <- profiled
    scan_sums_kernel<<<1, 128>>>(nsb, N);                          // 4
    scan_add_kernel<<<nsb, SCAN_BLK>>>(N);                         // 5
    scatter_kernel<<<(E + 511) / 512, 512>>>(rows, cols, vals, E); // 6
    int warps_per_block = 256 / 32;
    int sgrid = (N + warps_per_block - 1) / warps_per_block;
    spmm_relu_kernel<<<sgrid, 256>>>(out, N);                      // 7
}

// round 12
// speedup vs baseline: 1.0383x; 1.0217x over previous
#include <cuda_runtime.h>
#include <cuda_fp16.h>
#include <cuda_bf16.h>
#include <mma.h>

using namespace nvcuda;

// Problem constants.
#define EMB 256
#define MAX_NODES 100000
#define MAX_EDGES 3200000
#define SCAN_BLK 1024
#define MAX_SCAN_BLOCKS 128

// -------- device scratch (no allocations allowed) --------
__device__ __half d_Ph[MAX_NODES * EMB];  // P = emb @ W in fp16 (51.2 MB)
__device__ int   d_rowptr[MAX_NODES + 1];
__device__ int   d_cursor[MAX_NODES + 1];
__device__ int2  d_edge[MAX_EDGES];       // (col, bitcast(val))
__device__ int   d_blocksums[MAX_SCAN_BLOCKS];
__device__ int   d_blockoffs[MAX_SCAN_BLOCKS];

// ---------------- K0: zero counts ----------------
__global__ void zero_counts_kernel(int n) {
    int i = blockIdx.x * blockDim.x + threadIdx.x;
    if (i <= n) d_cursor[i] = 0;
}

// ---------------- K1: histogram of rows ----------------
__global__ void hist_kernel(const int* __restrict__ rows, int E) {
    int e = blockIdx.x * blockDim.x + threadIdx.x;
    if (e < E) atomicAdd(&d_cursor[rows[e]], 1);
}

// ---------------- scan helpers ----------------
__device__ __forceinline__ int warp_incl_scan(int v, int lane) {
    #pragma unroll
    for (int off = 1; off < 32; off <<= 1) {
        int x = __shfl_up_sync(0xffffffffu, v, off);
        if (lane >= off) v += x;
    }
    return v;
}

__global__ __launch_bounds__(SCAN_BLK) void scan_block_kernel(int n) {
    __shared__ int wsum[SCAN_BLK / 32];
    const int t = threadIdx.x;
    const int lane = t & 31;
    const int warp = t >> 5;
    const int i = blockIdx.x * SCAN_BLK + t;

    int v = (i < n) ? d_cursor[i] : 0;
    int incl = warp_incl_scan(v, lane);
    if (lane == 31) wsum[warp] = incl;
    __syncthreads();
    if (warp == 0) {
        int s = (lane < SCAN_BLK / 32) ? wsum[lane] : 0;
        s = warp_incl_scan(s, lane);
        if (lane < SCAN_BLK / 32) wsum[lane] = s;
    }
    __syncthreads();
    int base = (warp > 0) ? wsum[warp - 1] : 0;
    if (i < n) d_rowptr[i] = base + incl - v;
    if (t == SCAN_BLK - 1) d_blocksums[blockIdx.x] = base + incl;
}

__global__ __launch_bounds__(128) void scan_sums_kernel(int nblocks, int n) {
    __shared__ int wsum[4];
    const int t = threadIdx.x;
    const int lane = t & 31;
    const int warp = t >> 5;
    int v = (t < nblocks) ? d_blocksums[t] : 0;
    int incl = warp_incl_scan(v, lane);
    if (lane == 31) wsum[warp] = incl;
    __syncthreads();
    if (warp == 0) {
        int s = (lane < 4) ? wsum[lane] : 0;
        s = warp_incl_scan(s, lane);
        if (lane < 4) wsum[lane] = s;
    }
    __syncthreads();
    int base = (warp > 0) ? wsum[warp - 1] : 0;
    if (t < nblocks) d_blockoffs[t] = base + incl - v;
    if (t == 127) d_rowptr[n] = wsum[3];
}

__global__ __launch_bounds__(SCAN_BLK) void scan_add_kernel(int n) {
    const int i = blockIdx.x * SCAN_BLK + threadIdx.x;
    if (i < n) {
        int r = d_rowptr[i] + d_blockoffs[blockIdx.x];
        d_rowptr[i] = r;
        d_cursor[i] = r;
    }
}

// ---------------- K3: scatter edges into CSR order ----------------
__global__ void scatter_kernel(const int* __restrict__ rows,
                               const int* __restrict__ cols,
                               const float* __restrict__ vals, int E) {
    int e = blockIdx.x * blockDim.x + threadIdx.x;
    if (e < E) {
        int r = rows[e];
        int p = atomicAdd(&d_cursor[r], 1);
        d_edge[p] = make_int2(cols[e], __float_as_int(vals[e]));
    }
}

// ---------------- K4: persistent HMMA GEMM, W + full A block in smem ------
// 152 CTAs x 1024 threads. W (256x256 fp16) resident; each row-block stages
// the ENTIRE 128x256 A tile with BATCHED loads (explicit MLP-4 batches, no
// dependent convert between LDGs), then runs all 16 K-step MMAs barrier-free.
// Epilogue slab overlaps the A region (dead after the MMAs).
#define GBM 128
#define AB_LD 264   // 256 + 8 pad (halfs), 528B row stride (16B aligned)
#define E_LD 20     // 16 + 4 pad (floats), 80B row stride (16B aligned)

#define SM_W_BYTES  (256 * AB_LD * 2)           // 135168
#define SM_A_BYTES  (GBM * AB_LD * 2)           // 67584
#define SM_TOTAL    (SM_W_BYTES + SM_A_BYTES)   // 202752 (~198 KB)

extern __shared__ char gemm_smem[];

__global__ __launch_bounds__(1024, 1) void gemm_kernel(const float* __restrict__ A,
                                                       const float* __restrict__ W,
                                                       int M, int nblk) {
    __half (*sWm)[AB_LD] = reinterpret_cast<__half(*)[AB_LD]>(gemm_smem);
    __half (*sA)[AB_LD]  = reinterpret_cast<__half(*)[AB_LD]>(gemm_smem + SM_W_BYTES);
    float  (*sE)[16][E_LD] = reinterpret_cast<float(*)[16][E_LD]>(gemm_smem + SM_W_BYTES);

    const int tid = threadIdx.x;
    const int warp = tid >> 5;
    const int lane = tid & 31;
    const int warp_m = warp >> 3;   // 0..3 -> m offset 32*warp_m
    const int warp_n = warp & 7;    // 0..7 -> n offset 32*warp_n

    // Convert full W (256x256 fp32) into fp16 smem. 16384 float4, 16/thread.
    #pragma unroll
    for (int i = 0; i < 16; i++) {
        int g = tid + i * 1024;
        int r = g >> 6;            // 64 float4 per row
        int c4 = g & 63;
        float4 b = *reinterpret_cast<const float4*>(&W[r * EMB + c4 * 4]);
        __half2* dst = reinterpret_cast<__half2*>(&sWm[r][c4 * 4]);
        dst[0] = __floats2half2_rn(b.x, b.y);
        dst[1] = __floats2half2_rn(b.z, b.w);
    }

    const int er = lane >> 1;      // epilogue row in 16x16 frag
    const int ec0 = (lane & 1) * 8;

    for (int blk = blockIdx.x; blk < nblk; blk += gridDim.x) {
        const int row0 = blk * GBM;

        __syncthreads();   // previous epilogue (overlapping sA) fully read

        // Stage full A block: 128 x 256 fp32 -> fp16. 8192 float4, 8/thread,
        // in 2 batches of 4 INDEPENDENT loads (MLP 4+) before any convert/STS.
        #pragma unroll
        for (int b = 0; b < 2; b++) {
            float4 a[4];
            #pragma unroll
            for (int i = 0; i < 4; i++) {
                int g = tid + (b * 4 + i) * 1024;
                int r = g >> 6;
                a[i] = make_float4(0.f, 0.f, 0.f, 0.f);
                if (row0 + r < M)
                    a[i] = *reinterpret_cast<const float4*>(
                        &A[(long)(row0 + r) * EMB + (g & 63) * 4]);
            }
            #pragma unroll
            for (int i = 0; i < 4; i++) {
                int g = tid + (b * 4 + i) * 1024;
                int r = g >> 6;
                int c4 = g & 63;
                __half2* dst = reinterpret_cast<__half2*>(&sA[r][c4 * 4]);
                dst[0] = __floats2half2_rn(a[i].x, a[i].y);
                dst[1] = __floats2half2_rn(a[i].z, a[i].w);
            }
        }

        wmma::fragment<wmma::accumulator, 16, 16, 16, float> acc[2][2];
        #pragma unroll
        for (int i = 0; i < 2; i++)
            #pragma unroll
            for (int j = 0; j < 2; j++) wmma::fill_fragment(acc[i][j], 0.f);

        __syncthreads();   // sA ready

        // All 16 K-steps, zero barriers.
        #pragma unroll
        for (int ks = 0; ks < 16; ks++) {
            wmma::fragment<wmma::matrix_a, 16, 16, 16, __half, wmma::row_major> af[2];
            #pragma unroll
            for (int i = 0; i < 2; i++)
                wmma::load_matrix_sync(af[i], &sA[warp_m * 32 + i * 16][ks * 16], AB_LD);
            #pragma unroll
            for (int j = 0; j < 2; j++) {
                wmma::fragment<wmma::matrix_b, 16, 16, 16, __half, wmma::row_major> bf;
                wmma::load_matrix_sync(bf, &sWm[ks * 16][warp_n * 32 + j * 16], AB_LD);
                #pragma unroll
                for (int i = 0; i < 2; i++)
                    wmma::mma_sync(acc[i][j], af[i], bf, acc[i][j]);
            }
        }

        __syncthreads();   // all MMAs done reading sA; epilogue may overwrite

        // Per-warp epilogue: bounce each 16x16 frag through private slab.
        #pragma unroll
        for (int i = 0; i < 2; i++) {
            #pragma unroll
            for (int j = 0; j < 2; j++) {
                wmma::store_matrix_sync(&sE[warp][0][0], acc[i][j], E_LD, wmma::mem_row_major);
                __syncwarp();
                int g_r = row0 + warp_m * 32 + i * 16 + er;
                if (g_r < M) {
                    float4 v0 = *reinterpret_cast<const float4*>(&sE[warp][er][ec0]);
                    float4 v1 = *reinterpret_cast<const float4*>(&sE[warp][er][ec0 + 4]);
                    __half2 h[4] = {__floats2half2_rn(v0.x, v0.y), __floats2half2_rn(v0.z, v0.w),
                                    __floats2half2_rn(v1.x, v1.y), __floats2half2_rn(v1.z, v1.w)};
                    *reinterpret_cast<uint4*>(&d_Ph[(long)g_r * EMB + warp_n * 32 + j * 16 + ec0]) =
                        *reinterpret_cast<uint4*>(h);
                }
                __syncwarp();
            }
        }
    }
}

// ---------------- K5: SpMM in fp16-P space + ReLU -> fp32 out ----------------
__global__ __launch_bounds__(256) void spmm_relu_kernel(float* __restrict__ out,
                                                        int nrows) {
    const int warp = blockIdx.x * (blockDim.x >> 5) + (threadIdx.x >> 5);
    if (warp >= nrows) return;
    const int lane = threadIdx.x & 31;
    const int s = d_rowptr[warp];
    const int e = d_rowptr[warp + 1];

    float acc[8];
    #pragma unroll
    for (int i = 0; i < 8; i++) acc[i] = 0.f;

    const uint4* __restrict__ Pv = reinterpret_cast<const uint4*>(d_Ph);

    for (int base = s; base < e; base += 32) {
        int idx = base + lane;
        int c = 0;
        float v = 0.f;
        if (idx < e) {
            int2 ev = d_edge[idx];
            c = ev.x;
            v = __int_as_float(ev.y);
        }
        int cnt = e - base; if (cnt > 32) cnt = 32;
        #pragma unroll 2
        for (int j = 0; j < cnt; j++) {
            int   cj = __shfl_sync(0xffffffffu, c, j);
            float vj = __shfl_sync(0xffffffffu, v, j);
            uint4 q = Pv[(long)cj * 32 + lane];
            float2 f0 = __half22float2(*reinterpret_cast<__half2*>(&q.x));
            float2 f1 = __half22float2(*reinterpret_cast<__half2*>(&q.y));
            float2 f2 = __half22float2(*reinterpret_cast<__half2*>(&q.z));
            float2 f3 = __half22float2(*reinterpret_cast<__half2*>(&q.w));
            acc[0] = fmaf(vj, f0.x, acc[0]);
            acc[1] = fmaf(vj, f0.y, acc[1]);
            acc[2] = fmaf(vj, f1.x, acc[2]);
            acc[3] = fmaf(vj, f1.y, acc[3]);
            acc[4] = fmaf(vj, f2.x, acc[4]);
            acc[5] = fmaf(vj, f2.y, acc[5]);
            acc[6] = fmaf(vj, f3.x, acc[6]);
            acc[7] = fmaf(vj, f3.y, acc[7]);
        }
    }
    float4 o0 = {fmaxf(acc[0], 0.f), fmaxf(acc[1], 0.f), fmaxf(acc[2], 0.f), fmaxf(acc[3], 0.f)};
    float4 o1 = {fmaxf(acc[4], 0.f), fmaxf(acc[5], 0.f), fmaxf(acc[6], 0.f), fmaxf(acc[7], 0.f)};
    float4* outv = reinterpret_cast<float4*>(out);
    outv[(long)warp * 64 + lane * 2]     = o0;
    outv[(long)warp * 64 + lane * 2 + 1] = o1;
}

// ---------------- launch ----------------
extern "C" void kernel_launch(void* const* d_in, const int* in_sizes, int n_in,
                              void* d_out, int out_size) {
    const float* emb  = (const float*)d_in[0];
    const int*   rows = (const int*)  d_in[1];
    const int*   cols = (const int*)  d_in[2];
    const float* vals = (const float*)d_in[3];
    const float* W    = (const float*)d_in[4];
    float* out = (float*)d_out;

    const int N = in_sizes[0] / EMB;   // 100000
    const int E = in_sizes[1];         // 3200000

    const int nsb = (N + SCAN_BLK - 1) / SCAN_BLK;
    const int nblk = (N + GBM - 1) / GBM;

    cudaFuncSetAttribute(gemm_kernel, cudaFuncAttributeMaxDynamicSharedMemorySize, SM_TOTAL);

    // gemm_kernel stays launch idx 3 so ncu profiles it.
    zero_counts_kernel<<<(N + 256) / 256, 256>>>(N);               // 0
    hist_kernel<<<(E + 511) / 512, 512>>>(rows, E);                // 1
    scan_block_kernel<<<nsb, SCAN_BLK>>>(N);                       // 2
    gemm_kernel<<<152, 1024, SM_TOTAL>>>(emb, W, N, nblk);         // 3  <- profiled
    scan_sums_kernel<<<1, 128>>>(nsb, N);                          // 4
    scan_add_kernel<<<nsb, SCAN_BLK>>>(N);                         // 5
    scatter_kernel<<<(E + 511) / 512, 512>>>(rows, cols, vals, E); // 6
    int warps_per_block = 256 / 32;
    int sgrid = (N + warps_per_block - 1) / warps_per_block;
    spmm_relu_kernel<<<sgrid, 256>>>(out, N);                      // 7
}

// round 16
// speedup vs baseline: 1.0685x; 1.0291x over previous
#include <cuda_runtime.h>
#include <cuda_fp16.h>
#include <cuda_bf16.h>
#include <mma.h>

using namespace nvcuda;

// Problem constants.
#define EMB 256
#define MAX_NODES 100000
#define MAX_EDGES 3200000
#define SCAN_BLK 1024
#define MAX_SCAN_BLOCKS 128

// -------- device scratch (no allocations allowed) --------
__device__ __half d_Ph[MAX_NODES * EMB];  // P = emb @ W in fp16 (51.2 MB)
__device__ int   d_rowptr[MAX_NODES + 1];
__device__ int   d_cursor[MAX_NODES + 1];
__device__ int2  d_edge[MAX_EDGES];       // (col, bitcast(val))
__device__ int   d_blocksums[MAX_SCAN_BLOCKS];
__device__ int   d_blockoffs[MAX_SCAN_BLOCKS];

// ---------------- K0: zero counts ----------------
__global__ void zero_counts_kernel(int n) {
    int i = blockIdx.x * blockDim.x + threadIdx.x;
    if (i <= n) d_cursor[i] = 0;
}

// ---------------- K1: histogram of rows ----------------
__global__ void hist_kernel(const int* __restrict__ rows, int E) {
    int e = blockIdx.x * blockDim.x + threadIdx.x;
    if (e < E) atomicAdd(&d_cursor[rows[e]], 1);
}

// ---------------- scan helpers ----------------
__device__ __forceinline__ int warp_incl_scan(int v, int lane) {
    #pragma unroll
    for (int off = 1; off < 32; off <<= 1) {
        int x = __shfl_up_sync(0xffffffffu, v, off);
        if (lane >= off) v += x;
    }
    return v;
}

__global__ __launch_bounds__(SCAN_BLK) void scan_block_kernel(int n) {
    __shared__ int wsum[SCAN_BLK / 32];
    const int t = threadIdx.x;
    const int lane = t & 31;
    const int warp = t >> 5;
    const int i = blockIdx.x * SCAN_BLK + t;

    int v = (i < n) ? d_cursor[i] : 0;
    int incl = warp_incl_scan(v, lane);
    if (lane == 31) wsum[warp] = incl;
    __syncthreads();
    if (warp == 0) {
        int s = (lane < SCAN_BLK / 32) ? wsum[lane] : 0;
        s = warp_incl_scan(s, lane);
        if (lane < SCAN_BLK / 32) wsum[lane] = s;
    }
    __syncthreads();
    int base = (warp > 0) ? wsum[warp - 1] : 0;
    if (i < n) d_rowptr[i] = base + incl - v;
    if (t == SCAN_BLK - 1) d_blocksums[blockIdx.x] = base + incl;
}

__global__ __launch_bounds__(128) void scan_sums_kernel(int nblocks, int n) {
    __shared__ int wsum[4];
    const int t = threadIdx.x;
    const int lane = t & 31;
    const int warp = t >> 5;
    int v = (t < nblocks) ? d_blocksums[t] : 0;
    int incl = warp_incl_scan(v, lane);
    if (lane == 31) wsum[warp] = incl;
    __syncthreads();
    if (warp == 0) {
        int s = (lane < 4) ? wsum[lane] : 0;
        s = warp_incl_scan(s, lane);
        if (lane < 4) wsum[lane] = s;
    }
    __syncthreads();
    int base = (warp > 0) ? wsum[warp - 1] : 0;
    if (t < nblocks) d_blockoffs[t] = base + incl - v;
    if (t == 127) d_rowptr[n] = wsum[3];
}

__global__ __launch_bounds__(SCAN_BLK) void scan_add_kernel(int n) {
    const int i = blockIdx.x * SCAN_BLK + threadIdx.x;
    if (i < n) {
        int r = d_rowptr[i] + d_blockoffs[blockIdx.x];
        d_rowptr[i] = r;
        d_cursor[i] = r;
    }
}

// ---------------- K3: scatter edges into CSR order ----------------
__global__ void scatter_kernel(const int* __restrict__ rows,
                               const int* __restrict__ cols,
                               const float* __restrict__ vals, int E) {
    int e = blockIdx.x * blockDim.x + threadIdx.x;
    if (e < E) {
        int r = rows[e];
        int p = atomicAdd(&d_cursor[r], 1);
        d_edge[p] = make_int2(cols[e], __float_as_int(vals[e]));
    }
}

// ---------------- K4: persistent HMMA GEMM, W + full A block in smem ------
#define GBM 128
#define AB_LD 264   // 256 + 8 pad (halfs), 528B row stride (16B aligned)
#define E_LD 20     // 16 + 4 pad (floats), 80B row stride (16B aligned)

#define SM_W_BYTES  (256 * AB_LD * 2)           // 135168
#define SM_A_BYTES  (GBM * AB_LD * 2)           // 67584
#define SM_TOTAL    (SM_W_BYTES + SM_A_BYTES)   // 202752 (~198 KB)

extern __shared__ char gemm_smem[];

__global__ __launch_bounds__(1024, 1) void gemm_kernel(const float* __restrict__ A,
                                                       const float* __restrict__ W,
                                                       int M, int nblk) {
    __half (*sWm)[AB_LD] = reinterpret_cast<__half(*)[AB_LD]>(gemm_smem);
    __half (*sA)[AB_LD]  = reinterpret_cast<__half(*)[AB_LD]>(gemm_smem + SM_W_BYTES);
    float  (*sE)[16][E_LD] = reinterpret_cast<float(*)[16][E_LD]>(gemm_smem + SM_W_BYTES);

    const int tid = threadIdx.x;
    const int warp = tid >> 5;
    const int lane = tid & 31;
    const int warp_m = warp >> 3;
    const int warp_n = warp & 7;

    #pragma unroll
    for (int i = 0; i < 16; i++) {
        int g = tid + i * 1024;
        int r = g >> 6;
        int c4 = g & 63;
        float4 b = *reinterpret_cast<const float4*>(&W[r * EMB + c4 * 4]);
        __half2* dst = reinterpret_cast<__half2*>(&sWm[r][c4 * 4]);
        dst[0] = __floats2half2_rn(b.x, b.y);
        dst[1] = __floats2half2_rn(b.z, b.w);
    }

    const int er = lane >> 1;
    const int ec0 = (lane & 1) * 8;

    for (int blk = blockIdx.x; blk < nblk; blk += gridDim.x) {
        const int row0 = blk * GBM;

        __syncthreads();

        #pragma unroll
        for (int b = 0; b < 2; b++) {
            float4 a[4];
            #pragma unroll
            for (int i = 0; i < 4; i++) {
                int g = tid + (b * 4 + i) * 1024;
                int r = g >> 6;
                a[i] = make_float4(0.f, 0.f, 0.f, 0.f);
                if (row0 + r < M)
                    a[i] = *reinterpret_cast<const float4*>(
                        &A[(long)(row0 + r) * EMB + (g & 63) * 4]);
            }
            #pragma unroll
            for (int i = 0; i < 4; i++) {
                int g = tid + (b * 4 + i) * 1024;
                int r = g >> 6;
                int c4 = g & 63;
                __half2* dst = reinterpret_cast<__half2*>(&sA[r][c4 * 4]);
                dst[0] = __floats2half2_rn(a[i].x, a[i].y);
                dst[1] = __floats2half2_rn(a[i].z, a[i].w);
            }
        }

        wmma::fragment<wmma::accumulator, 16, 16, 16, float> acc[2][2];
        #pragma unroll
        for (int i = 0; i < 2; i++)
            #pragma unroll
            for (int j = 0; j < 2; j++) wmma::fill_fragment(acc[i][j], 0.f);

        __syncthreads();

        #pragma unroll
        for (int ks = 0; ks < 16; ks++) {
            wmma::fragment<wmma::matrix_a, 16, 16, 16, __half, wmma::row_major> af[2];
            #pragma unroll
            for (int i = 0; i < 2; i++)
                wmma::load_matrix_sync(af[i], &sA[warp_m * 32 + i * 16][ks * 16], AB_LD);
            #pragma unroll
            for (int j = 0; j < 2; j++) {
                wmma::fragment<wmma::matrix_b, 16, 16, 16, __half, wmma::row_major> bf;
                wmma::load_matrix_sync(bf, &sWm[ks * 16][warp_n * 32 + j * 16], AB_LD);
                #pragma unroll
                for (int i = 0; i < 2; i++)
                    wmma::mma_sync(acc[i][j], af[i], bf, acc[i][j]);
            }
        }

        __syncthreads();

        #pragma unroll
        for (int i = 0; i < 2; i++) {
            #pragma unroll
            for (int j = 0; j < 2; j++) {
                wmma::store_matrix_sync(&sE[warp][0][0], acc[i][j], E_LD, wmma::mem_row_major);
                __syncwarp();
                int g_r = row0 + warp_m * 32 + i * 16 + er;
                if (g_r < M) {
                    float4 v0 = *reinterpret_cast<const float4*>(&sE[warp][er][ec0]);
                    float4 v1 = *reinterpret_cast<const float4*>(&sE[warp][er][ec0 + 4]);
                    __half2 h[4] = {__floats2half2_rn(v0.x, v0.y), __floats2half2_rn(v0.z, v0.w),
                                    __floats2half2_rn(v1.x, v1.y), __floats2half2_rn(v1.z, v1.w)};
                    *reinterpret_cast<uint4*>(&d_Ph[(long)g_r * EMB + warp_n * 32 + j * 16 + ec0]) =
                        *reinterpret_cast<uint4*>(h);
                }
                __syncwarp();
            }
        }
    }
}

// ---------------- K5: SpMM in fp16-P space + ReLU -> fp32 out ----------------
// One warp per row. Inner loop processes edges in PAIRS: both 512B gathers
// issued back-to-back (independent) before any FMA -> explicit MLP 2+.
__global__ __launch_bounds__(256) void spmm_relu_kernel(float* __restrict__ out,
                                                        int nrows) {
    const int warp = blockIdx.x * (blockDim.x >> 5) + (threadIdx.x >> 5);
    if (warp >= nrows) return;
    const int lane = threadIdx.x & 31;
    const int s = d_rowptr[warp];
    const int e = d_rowptr[warp + 1];

    float acc[8];
    #pragma unroll
    for (int i = 0; i < 8; i++) acc[i] = 0.f;

    const uint4* __restrict__ Pv = reinterpret_cast<const uint4*>(d_Ph);

    for (int base = s; base < e; base += 32) {
        int idx = base + lane;
        int c = 0;
        float v = 0.f;
        if (idx < e) {
            int2 ev = d_edge[idx];
            c = ev.x;
            v = __int_as_float(ev.y);
        }
        int cnt = e - base; if (cnt > 32) cnt = 32;

        int j = 0;
        #pragma unroll 2
        for (; j + 1 < cnt; j += 2) {
            int   cj0 = __shfl_sync(0xffffffffu, c, j);
            float vj0 = __shfl_sync(0xffffffffu, v, j);
            int   cj1 = __shfl_sync(0xffffffffu, c, j + 1);
            float vj1 = __shfl_sync(0xffffffffu, v, j + 1);
            uint4 q0 = Pv[(long)cj0 * 32 + lane];
            uint4 q1 = Pv[(long)cj1 * 32 + lane];
            {
                float2 f0 = __half22float2(*reinterpret_cast<__half2*>(&q0.x));
                float2 f1 = __half22float2(*reinterpret_cast<__half2*>(&q0.y));
                float2 f2 = __half22float2(*reinterpret_cast<__half2*>(&q0.z));
                float2 f3 = __half22float2(*reinterpret_cast<__half2*>(&q0.w));
                acc[0] = fmaf(vj0, f0.x, acc[0]);
                acc[1] = fmaf(vj0, f0.y, acc[1]);
                acc[2] = fmaf(vj0, f1.x, acc[2]);
                acc[3] = fmaf(vj0, f1.y, acc[3]);
                acc[4] = fmaf(vj0, f2.x, acc[4]);
                acc[5] = fmaf(vj0, f2.y, acc[5]);
                acc[6] = fmaf(vj0, f3.x, acc[6]);
                acc[7] = fmaf(vj0, f3.y, acc[7]);
            }
            {
                float2 f0 = __half22float2(*reinterpret_cast<__half2*>(&q1.x));
                float2 f1 = __half22float2(*reinterpret_cast<__half2*>(&q1.y));
                float2 f2 = __half22float2(*reinterpret_cast<__half2*>(&q1.z));
                float2 f3 = __half22float2(*reinterpret_cast<__half2*>(&q1.w));
                acc[0] = fmaf(vj1, f0.x, acc[0]);
                acc[1] = fmaf(vj1, f0.y, acc[1]);
                acc[2] = fmaf(vj1, f1.x, acc[2]);
                acc[3] = fmaf(vj1, f1.y, acc[3]);
                acc[4] = fmaf(vj1, f2.x, acc[4]);
                acc[5] = fmaf(vj1, f2.y, acc[5]);
                acc[6] = fmaf(vj1, f3.x, acc[6]);
                acc[7] = fmaf(vj1, f3.y, acc[7]);
            }
        }
        if (j < cnt) {
            int   cj = __shfl_sync(0xffffffffu, c, j);
            float vj = __shfl_sync(0xffffffffu, v, j);
            uint4 q = Pv[(long)cj * 32 + lane];
            float2 f0 = __half22float2(*reinterpret_cast<__half2*>(&q.x));
            float2 f1 = __half22float2(*reinterpret_cast<__half2*>(&q.y));
            float2 f2 = __half22float2(*reinterpret_cast<__half2*>(&q.z));
            float2 f3 = __half22float2(*reinterpret_cast<__half2*>(&q.w));
            acc[0] = fmaf(vj, f0.x, acc[0]);
            acc[1] = fmaf(vj, f0.y, acc[1]);
            acc[2] = fmaf(vj, f1.x, acc[2]);
            acc[3] = fmaf(vj, f1.y, acc[3]);
            acc[4] = fmaf(vj, f2.x, acc[4]);
            acc[5] = fmaf(vj, f2.y, acc[5]);
            acc[6] = fmaf(vj, f3.x, acc[6]);
            acc[7] = fmaf(vj, f3.y, acc[7]);
        }
    }
    float4 o0 = {fmaxf(acc[0], 0.f), fmaxf(acc[1], 0.f), fmaxf(acc[2], 0.f), fmaxf(acc[3], 0.f)};
    float4 o1 = {fmaxf(acc[4], 0.f), fmaxf(acc[5], 0.f), fmaxf(acc[6], 0.f), fmaxf(acc[7], 0.f)};
    float4* outv = reinterpret_cast<float4*>(out);
    outv[(long)warp * 64 + lane * 2]     = o0;
    outv[(long)warp * 64 + lane * 2 + 1] = o1;
}

// ---------------- launch ----------------
extern "C" void kernel_launch(void* const* d_in, const int* in_sizes, int n_in,
                              void* d_out, int out_size) {
    const float* emb  = (const float*)d_in[0];
    const int*   rows = (const int*)  d_in[1];
    const int*   cols = (const int*)  d_in[2];
    const float* vals = (const float*)d_in[3];
    const float* W    = (const float*)d_in[4];
    float* out = (float*)d_out;

    const int N = in_sizes[0] / EMB;   // 100000
    const int E = in_sizes[1];         // 3200000

    const int nsb = (N + SCAN_BLK - 1) / SCAN_BLK;
    const int nblk = (N + GBM - 1) / GBM;

    cudaFuncSetAttribute(gemm_kernel, cudaFuncAttributeMaxDynamicSharedMemorySize, SM_TOTAL);

    // gemm_kernel stays launch idx 3 so ncu profiles it.
    zero_counts_kernel<<<(N + 256) / 256, 256>>>(N);               // 0
    hist_kernel<<<(E + 511) / 512, 512>>>(rows, E);                // 1
    scan_block_kernel<<<nsb, SCAN_BLK>>>(N);                       // 2
    gemm_kernel<<<152, 1024, SM_TOTAL>>>(emb, W, N, nblk);         // 3  <- profiled
    scan_sums_kernel<<<1, 128>>>(nsb, N);                          // 4
    scan_add_kernel<<<nsb, SCAN_BLK>>>(N);                         // 5
    scatter_kernel<<<(E + 511) / 512, 512>>>(rows, cols, vals, E); // 6
    int warps_per_block = 256 / 32;
    int sgrid = (N + warps_per_block - 1) / warps_per_block;
    spmm_relu_kernel<<<sgrid, 256>>>(out, N);                      // 7
}